// round 1
// baseline (speedup 1.0000x reference)
#include <cuda_runtime.h>

#define BB 64
#define HH 256
#define WW 256
#define CC 3
#define KK 20
#define HWPIX (HH * WW)
#define BLOCKS_PER_IMG 128   // each block covers 2 rows (512 pixels)

// Deterministic reduction scratch (device globals: allowed, no allocation)
__device__ float g_partial[BB][BLOCKS_PER_IMG][3];
__device__ float g_mean[BB][3];

// ---------------------------------------------------------------------------
// Kernel 1: affine bilinear warp -> out, plus per-block partial channel sums
// ---------------------------------------------------------------------------
__global__ __launch_bounds__(256) void k_warp(
    const float* __restrict__ img,
    const float* __restrict__ zoom, const float* __restrict__ rot,
    const float* __restrict__ shy,  const float* __restrict__ ty,
    const float* __restrict__ tx,
    float* __restrict__ out)
{
    const int b   = blockIdx.y;
    const int blk = blockIdx.x;          // 0..127
    const int t   = threadIdx.x;         // 0..255

    const float z  = zoom[b];
    const float r  = rot[b];
    const float sh = shy[b];
    const float co = cosf(r), si = sinf(r);
    const float a0 = z * co;
    const float a1 = -z * (si + sh);
    const float b0 = z * si;
    const float b1 = z * co;
    const float cx = (WW - 1) * 0.5f, cy = (HH - 1) * 0.5f;
    const float a2 = -a0 * cx - a1 * cy + cx + tx[b];
    const float b2 = -b0 * cx - b1 * cy + cy + ty[b];

    const float* __restrict__ imgb = img + (size_t)b * HWPIX * CC;
    float* __restrict__ outb = out + (size_t)b * HWPIX * CC;

    float s0 = 0.f, s1 = 0.f, s2 = 0.f;

#pragma unroll
    for (int pp = 0; pp < 2; pp++) {
        const int p = blk * 512 + pp * 256 + t;   // pixel index within image
        const int y = p >> 8;                     // W == 256
        const int x = p & 255;

        const float xf = (float)x, yf = (float)y;
        const float xs = a0 * xf + a1 * yf + a2;
        const float ys = b0 * xf + b1 * yf + b2;
        const float x0f = floorf(xs);
        const float y0f = floorf(ys);
        const float wx = xs - x0f;
        const float wy = ys - y0f;
        const int x0i = (int)x0f;
        const int y0i = (int)y0f;

        float v00[3], v01[3], v10[3], v11[3];

        // fetch corner with zero-outside semantics (clamped addr, masked value)
        auto fetch = [&](int yi, int xi, float* v) {
            const bool val = ((unsigned)yi < (unsigned)HH) && ((unsigned)xi < (unsigned)WW);
            const int yc = min(max(yi, 0), HH - 1);
            const int xc = min(max(xi, 0), WW - 1);
            const float m = val ? 1.0f : 0.0f;
            const float* pptr = imgb + (yc * WW + xc) * CC;
            v[0] = pptr[0] * m;
            v[1] = pptr[1] * m;
            v[2] = pptr[2] * m;
        };

        fetch(y0i,     x0i,     v00);
        fetch(y0i,     x0i + 1, v01);
        fetch(y0i + 1, x0i,     v10);
        fetch(y0i + 1, x0i + 1, v11);

        const float w00 = (1.f - wy) * (1.f - wx);
        const float w01 = (1.f - wy) * wx;
        const float w10 = wy * (1.f - wx);
        const float w11 = wy * wx;

        float* op = outb + p * CC;
        const float o0 = w00 * v00[0] + w01 * v01[0] + w10 * v10[0] + w11 * v11[0];
        const float o1 = w00 * v00[1] + w01 * v01[1] + w10 * v10[1] + w11 * v11[1];
        const float o2 = w00 * v00[2] + w01 * v01[2] + w10 * v10[2] + w11 * v11[2];
        op[0] = o0; op[1] = o1; op[2] = o2;
        s0 += o0; s1 += o1; s2 += o2;
    }

    // Deterministic block reduction: warp shuffle then smem tree
    __shared__ float sm[8][3];
    const int lane = t & 31;
    const int wrp  = t >> 5;
#pragma unroll
    for (int off = 16; off > 0; off >>= 1) {
        s0 += __shfl_down_sync(0xffffffffu, s0, off);
        s1 += __shfl_down_sync(0xffffffffu, s1, off);
        s2 += __shfl_down_sync(0xffffffffu, s2, off);
    }
    if (lane == 0) { sm[wrp][0] = s0; sm[wrp][1] = s1; sm[wrp][2] = s2; }
    __syncthreads();
    if (wrp == 0 && lane < 8) {
        float t0 = sm[lane][0], t1 = sm[lane][1], t2 = sm[lane][2];
#pragma unroll
        for (int off = 4; off > 0; off >>= 1) {
            t0 += __shfl_down_sync(0xffu, t0, off);
            t1 += __shfl_down_sync(0xffu, t1, off);
            t2 += __shfl_down_sync(0xffu, t2, off);
        }
        if (lane == 0) {
            g_partial[b][blk][0] = t0;
            g_partial[b][blk][1] = t1;
            g_partial[b][blk][2] = t2;
        }
    }
}

// ---------------------------------------------------------------------------
// Kernel 2: reduce 128 partials per image -> per-channel mean
// ---------------------------------------------------------------------------
__global__ __launch_bounds__(128) void k_reduce()
{
    const int b = blockIdx.x;
    const int t = threadIdx.x;   // 0..127
    float s0 = g_partial[b][t][0];
    float s1 = g_partial[b][t][1];
    float s2 = g_partial[b][t][2];

    __shared__ float sm[4][3];
    const int lane = t & 31;
    const int wrp  = t >> 5;
#pragma unroll
    for (int off = 16; off > 0; off >>= 1) {
        s0 += __shfl_down_sync(0xffffffffu, s0, off);
        s1 += __shfl_down_sync(0xffffffffu, s1, off);
        s2 += __shfl_down_sync(0xffffffffu, s2, off);
    }
    if (lane == 0) { sm[wrp][0] = s0; sm[wrp][1] = s1; sm[wrp][2] = s2; }
    __syncthreads();
    if (t == 0) {
        const float inv = 1.0f / (float)HWPIX;
        g_mean[b][0] = (sm[0][0] + sm[1][0] + sm[2][0] + sm[3][0]) * inv;
        g_mean[b][1] = (sm[0][1] + sm[1][1] + sm[2][1] + sm[3][1]) * inv;
        g_mean[b][2] = (sm[0][2] + sm[1][2] + sm[2][2] + sm[3][2]) * inv;
    }
}

// ---------------------------------------------------------------------------
// Kernel 3: contrast/brightness + cutouts + clip, in place on out
// ---------------------------------------------------------------------------
__global__ __launch_bounds__(256) void k_epilogue(
    const float* __restrict__ contrast, const float* __restrict__ brightness,
    const float* __restrict__ fill_is_one,
    const int* __restrict__ hs, const int* __restrict__ ws,
    const int* __restrict__ y0, const int* __restrict__ x0,
    float* __restrict__ out)
{
    const int b   = blockIdx.y;
    const int blk = blockIdx.x;          // 0..127
    const int t   = threadIdx.x;         // 0..255

    __shared__ int   ry0[KK], ry1[KK], rx0[KK], rx1[KK];
    __shared__ int   rfill[KK];

    if (t < KK) {
        const int k  = t;
        const int hk = hs[b * KK + k];
        const int wk = ws[b * KK + k];
        int y0c = y0[b * KK + k]; if (y0c > HH - hk) y0c = HH - hk;
        int x0c = x0[b * KK + k]; if (x0c > WW - wk) x0c = WW - wk;
        ry0[k] = y0c; ry1[k] = y0c + hk;
        rx0[k] = x0c; rx1[k] = x0c + wk;
        rfill[k] = (fill_is_one[b * KK + k] > 0.5f) ? 1 : 0;
    }
    __syncthreads();

    const float m0 = g_mean[b][0];
    const float m1 = g_mean[b][1];
    const float m2 = g_mean[b][2];
    const float ct = contrast[b];
    const float br = brightness[b];

    float* __restrict__ outb = out + (size_t)b * HWPIX * CC;

#pragma unroll
    for (int pp = 0; pp < 2; pp++) {
        const int p = blk * 512 + pp * 256 + t;
        const int y = p >> 8;
        const int x = p & 255;

        bool erase = false, blot = false;
#pragma unroll
        for (int k = 0; k < KK; k++) {
            const bool in = (y >= ry0[k]) & (y < ry1[k]) & (x >= rx0[k]) & (x < rx1[k]);
            if (rfill[k]) blot  |= in;
            else          erase |= in;
        }

        float* op = outb + p * CC;
        float v0 = op[0], v1 = op[1], v2 = op[2];
        v0 = (v0 - m0) * ct + m0 + br;
        v1 = (v1 - m1) * ct + m1 + br;
        v2 = (v2 - m2) * ct + m2 + br;
        if (erase) { v0 = 0.f; v1 = 0.f; v2 = 0.f; }
        if (blot)  { v0 = 1.f; v1 = 1.f; v2 = 1.f; }
        v0 = fminf(fmaxf(v0, 0.f), 1.f);
        v1 = fminf(fmaxf(v1, 0.f), 1.f);
        v2 = fminf(fmaxf(v2, 0.f), 1.f);
        op[0] = v0; op[1] = v1; op[2] = v2;
    }
}

// ---------------------------------------------------------------------------
extern "C" void kernel_launch(void* const* d_in, const int* in_sizes, int n_in,
                              void* d_out, int out_size)
{
    const float* images     = (const float*)d_in[0];
    const float* zoom       = (const float*)d_in[1];
    const float* rot        = (const float*)d_in[2];
    const float* shy        = (const float*)d_in[3];
    const float* ty         = (const float*)d_in[4];
    const float* tx         = (const float*)d_in[5];
    const float* contrast   = (const float*)d_in[6];
    const float* brightness = (const float*)d_in[7];
    const float* fill       = (const float*)d_in[8];
    const int*   hs         = (const int*)d_in[9];
    const int*   ws         = (const int*)d_in[10];
    const int*   y0         = (const int*)d_in[11];
    const int*   x0         = (const int*)d_in[12];
    float* out = (float*)d_out;

    dim3 grid(BLOCKS_PER_IMG, BB);
    k_warp<<<grid, 256>>>(images, zoom, rot, shy, ty, tx, out);
    k_reduce<<<BB, 128>>>();
    k_epilogue<<<grid, 256>>>(contrast, brightness, fill, hs, ws, y0, x0, out);
}

// round 2
// speedup vs baseline: 1.2545x; 1.2545x over previous
#include <cuda_runtime.h>

#define BB 64
#define HH 256
#define WW 256
#define CC 3
#define KK 20
#define HWPIX (HH * WW)
#define BLOCKS_PER_IMG 128   // k_warp: each block covers 2 rows (512 pixels)

// Scratch (device globals: allowed, no allocation)
__device__ float g_partial[BB][BLOCKS_PER_IMG][3];
__device__ float g_mean[BB][3];
__device__ unsigned g_emask[BB][HH][8];   // per-row 256-bit erase mask
__device__ unsigned g_bmask[BB][HH][8];   // per-row 256-bit blot mask

// ---------------------------------------------------------------------------
// Kernel 1: affine bilinear warp -> out, plus per-block partial channel sums
// (unchanged from R1 — L1tex-bound; to be optimized next round)
// ---------------------------------------------------------------------------
__global__ __launch_bounds__(256) void k_warp(
    const float* __restrict__ img,
    const float* __restrict__ zoom, const float* __restrict__ rot,
    const float* __restrict__ shy,  const float* __restrict__ ty,
    const float* __restrict__ tx,
    float* __restrict__ out)
{
    const int b   = blockIdx.y;
    const int blk = blockIdx.x;          // 0..127
    const int t   = threadIdx.x;         // 0..255

    const float z  = zoom[b];
    const float r  = rot[b];
    const float sh = shy[b];
    const float co = cosf(r), si = sinf(r);
    const float a0 = z * co;
    const float a1 = -z * (si + sh);
    const float b0 = z * si;
    const float b1 = z * co;
    const float cx = (WW - 1) * 0.5f, cy = (HH - 1) * 0.5f;
    const float a2 = -a0 * cx - a1 * cy + cx + tx[b];
    const float b2 = -b0 * cx - b1 * cy + cy + ty[b];

    const float* __restrict__ imgb = img + (size_t)b * HWPIX * CC;
    float* __restrict__ outb = out + (size_t)b * HWPIX * CC;

    float s0 = 0.f, s1 = 0.f, s2 = 0.f;

#pragma unroll
    for (int pp = 0; pp < 2; pp++) {
        const int p = blk * 512 + pp * 256 + t;   // pixel index within image
        const int y = p >> 8;                     // W == 256
        const int x = p & 255;

        const float xf = (float)x, yf = (float)y;
        const float xs = a0 * xf + a1 * yf + a2;
        const float ys = b0 * xf + b1 * yf + b2;
        const float x0f = floorf(xs);
        const float y0f = floorf(ys);
        const float wx = xs - x0f;
        const float wy = ys - y0f;
        const int x0i = (int)x0f;
        const int y0i = (int)y0f;

        float v00[3], v01[3], v10[3], v11[3];

        auto fetch = [&](int yi, int xi, float* v) {
            const bool val = ((unsigned)yi < (unsigned)HH) && ((unsigned)xi < (unsigned)WW);
            const int yc = min(max(yi, 0), HH - 1);
            const int xc = min(max(xi, 0), WW - 1);
            const float m = val ? 1.0f : 0.0f;
            const float* pptr = imgb + (yc * WW + xc) * CC;
            v[0] = pptr[0] * m;
            v[1] = pptr[1] * m;
            v[2] = pptr[2] * m;
        };

        fetch(y0i,     x0i,     v00);
        fetch(y0i,     x0i + 1, v01);
        fetch(y0i + 1, x0i,     v10);
        fetch(y0i + 1, x0i + 1, v11);

        const float w00 = (1.f - wy) * (1.f - wx);
        const float w01 = (1.f - wy) * wx;
        const float w10 = wy * (1.f - wx);
        const float w11 = wy * wx;

        float* op = outb + p * CC;
        const float o0 = w00 * v00[0] + w01 * v01[0] + w10 * v10[0] + w11 * v11[0];
        const float o1 = w00 * v00[1] + w01 * v01[1] + w10 * v10[1] + w11 * v11[1];
        const float o2 = w00 * v00[2] + w01 * v01[2] + w10 * v10[2] + w11 * v11[2];
        op[0] = o0; op[1] = o1; op[2] = o2;
        s0 += o0; s1 += o1; s2 += o2;
    }

    __shared__ float sm[8][3];
    const int lane = t & 31;
    const int wrp  = t >> 5;
#pragma unroll
    for (int off = 16; off > 0; off >>= 1) {
        s0 += __shfl_down_sync(0xffffffffu, s0, off);
        s1 += __shfl_down_sync(0xffffffffu, s1, off);
        s2 += __shfl_down_sync(0xffffffffu, s2, off);
    }
    if (lane == 0) { sm[wrp][0] = s0; sm[wrp][1] = s1; sm[wrp][2] = s2; }
    __syncthreads();
    if (wrp == 0 && lane < 8) {
        float t0 = sm[lane][0], t1 = sm[lane][1], t2 = sm[lane][2];
#pragma unroll
        for (int off = 4; off > 0; off >>= 1) {
            t0 += __shfl_down_sync(0xffu, t0, off);
            t1 += __shfl_down_sync(0xffu, t1, off);
            t2 += __shfl_down_sync(0xffu, t2, off);
        }
        if (lane == 0) {
            g_partial[b][blk][0] = t0;
            g_partial[b][blk][1] = t1;
            g_partial[b][blk][2] = t2;
        }
    }
}

// ---------------------------------------------------------------------------
// Kernel 2: per-image mean + per-row cutout bitmasks (one block per image)
// ---------------------------------------------------------------------------
__device__ __forceinline__ unsigned rmask(int x0, int x1, int lo)
{
    int s = x0 - lo; if (s < 0) s = 0;
    int e = x1 - lo; if (e > 32) e = 32;
    if (e <= s) return 0u;
    unsigned me = (e == 32) ? 0xffffffffu : ((1u << e) - 1u);
    unsigned ms = (s == 0)  ? 0u          : ((1u << s) - 1u);
    return me & ~ms;
}

__global__ __launch_bounds__(256) void k_mask(
    const float* __restrict__ fill_is_one,
    const int* __restrict__ hs, const int* __restrict__ ws,
    const int* __restrict__ y0, const int* __restrict__ x0)
{
    const int b = blockIdx.x;
    const int t = threadIdx.x;       // 0..255

    __shared__ int   ry0[KK], ry1[KK], rx0[KK], rx1[KK];
    __shared__ int   rfill[KK];
    __shared__ float smr[4][3];

    if (t < KK) {
        const int k  = t;
        const int hk = hs[b * KK + k];
        const int wk = ws[b * KK + k];
        int y0c = y0[b * KK + k]; if (y0c > HH - hk) y0c = HH - hk;
        int x0c = x0[b * KK + k]; if (x0c > WW - wk) x0c = WW - wk;
        ry0[k] = y0c; ry1[k] = y0c + hk;
        rx0[k] = x0c; rx1[k] = x0c + wk;
        rfill[k] = (fill_is_one[b * KK + k] > 0.5f) ? 1 : 0;
    }

    // mean reduce over 128 partials (threads 0..127 = warps 0..3)
    if (t < 128) {
        float s0 = g_partial[b][t][0];
        float s1 = g_partial[b][t][1];
        float s2 = g_partial[b][t][2];
        const int lane = t & 31;
        const int wrp  = t >> 5;
#pragma unroll
        for (int off = 16; off > 0; off >>= 1) {
            s0 += __shfl_down_sync(0xffffffffu, s0, off);
            s1 += __shfl_down_sync(0xffffffffu, s1, off);
            s2 += __shfl_down_sync(0xffffffffu, s2, off);
        }
        if (lane == 0) { smr[wrp][0] = s0; smr[wrp][1] = s1; smr[wrp][2] = s2; }
    }
    __syncthreads();
    if (t == 0) {
        const float inv = 1.0f / (float)HWPIX;
        g_mean[b][0] = (smr[0][0] + smr[1][0] + smr[2][0] + smr[3][0]) * inv;
        g_mean[b][1] = (smr[0][1] + smr[1][1] + smr[2][1] + smr[3][1]) * inv;
        g_mean[b][2] = (smr[0][2] + smr[1][2] + smr[2][2] + smr[3][2]) * inv;
    }

    // each thread builds the masks for one row
    const int y = t;
    unsigned em[8] = {0,0,0,0,0,0,0,0};
    unsigned bm[8] = {0,0,0,0,0,0,0,0};
#pragma unroll
    for (int k = 0; k < KK; k++) {
        if (y >= ry0[k] && y < ry1[k]) {
            const int xa = rx0[k], xb = rx1[k];
            if (rfill[k]) {
#pragma unroll
                for (int w = 0; w < 8; w++) bm[w] |= rmask(xa, xb, w * 32);
            } else {
#pragma unroll
                for (int w = 0; w < 8; w++) em[w] |= rmask(xa, xb, w * 32);
            }
        }
    }
#pragma unroll
    for (int w = 0; w < 8; w++) {
        g_emask[b][y][w] = em[w];
        g_bmask[b][y][w] = bm[w];
    }
}

// ---------------------------------------------------------------------------
// Kernel 3: contrast/brightness + cutout masks + clip, vectorized float4
// Each thread handles 4 pixels = 12 floats = 3 float4 (48B-aligned).
// Block = 256 threads = 1024 pixels = 4 rows. Grid = (64 row-groups, 64 imgs)
// ---------------------------------------------------------------------------
__global__ __launch_bounds__(256) void k_epilogue(
    const float* __restrict__ contrast, const float* __restrict__ brightness,
    float* __restrict__ out)
{
    const int b  = blockIdx.y;
    const int rg = blockIdx.x;           // 0..63, 4 rows each
    const int t  = threadIdx.x;          // 0..255

    __shared__ unsigned sew[4][8];
    __shared__ unsigned sbw[4][8];
    if (t < 64) {
        const int row = t >> 4;          // 0..3
        const int w   = t & 15;          // 0..15
        if (w < 8) sew[row][w] = g_emask[b][rg * 4 + row][w];
        else       sbw[row][w - 8] = g_bmask[b][rg * 4 + row][w - 8];
    }
    __syncthreads();

    const float m0 = g_mean[b][0];
    const float m1 = g_mean[b][1];
    const float m2 = g_mean[b][2];
    const float ct = contrast[b];
    const float br = brightness[b];

    const int p  = rg * 1024 + 4 * t;    // first pixel of this thread
    const int yl = t >> 6;               // row within block (0..3)
    const int x  = (4 * t) & 255;        // x of first pixel (multiple of 4)

    const unsigned ew = sew[yl][x >> 5] >> (x & 31);   // 4 bits: pixels x..x+3
    const unsigned bw = sbw[yl][x >> 5] >> (x & 31);

    float4* base = (float4*)(out + ((size_t)b * HWPIX + p) * CC);
    float4 fa = base[0];
    float4 fb = base[1];
    float4 fc = base[2];

    float v[12] = { fa.x, fa.y, fa.z, fa.w, fb.x, fb.y, fb.z, fb.w,
                    fc.x, fc.y, fc.z, fc.w };
    const float mm[3] = { m0, m1, m2 };

#pragma unroll
    for (int j = 0; j < 12; j++) {
        const int ch = j - (j >= 3) * 3 - (j >= 6) * 3 - (j >= 9) * 3; // j % 3
        const int px = j / 3;                                           // 0..3
        float val = (v[j] - mm[ch]) * ct + mm[ch] + br;
        if ((ew >> px) & 1u) val = 0.0f;
        if ((bw >> px) & 1u) val = 1.0f;
        v[j] = fminf(fmaxf(val, 0.0f), 1.0f);
    }

    fa = make_float4(v[0], v[1], v[2], v[3]);
    fb = make_float4(v[4], v[5], v[6], v[7]);
    fc = make_float4(v[8], v[9], v[10], v[11]);
    base[0] = fa;
    base[1] = fb;
    base[2] = fc;
}

// ---------------------------------------------------------------------------
extern "C" void kernel_launch(void* const* d_in, const int* in_sizes, int n_in,
                              void* d_out, int out_size)
{
    const float* images     = (const float*)d_in[0];
    const float* zoom       = (const float*)d_in[1];
    const float* rot        = (const float*)d_in[2];
    const float* shy        = (const float*)d_in[3];
    const float* ty         = (const float*)d_in[4];
    const float* tx         = (const float*)d_in[5];
    const float* contrast   = (const float*)d_in[6];
    const float* brightness = (const float*)d_in[7];
    const float* fill       = (const float*)d_in[8];
    const int*   hs         = (const int*)d_in[9];
    const int*   ws         = (const int*)d_in[10];
    const int*   y0         = (const int*)d_in[11];
    const int*   x0         = (const int*)d_in[12];
    float* out = (float*)d_out;

    dim3 gwarp(BLOCKS_PER_IMG, BB);
    k_warp<<<gwarp, 256>>>(images, zoom, rot, shy, ty, tx, out);
    k_mask<<<BB, 256>>>(fill, hs, ws, y0, x0);
    dim3 gepi(64, BB);
    k_epilogue<<<gepi, 256>>>(contrast, brightness, out);
}